// round 4
// baseline (speedup 1.0000x reference)
#include <cuda_runtime.h>

#define TPB 128
#define NH  40
#define NT  40
#define NG  160
#define NC  4
#define HBASE 3208   // floats per half-section: 80 rows * 40 + 8-float bank skew

typedef unsigned long long u64;

__device__ __forceinline__ u64 pack2(float lo, float hi) {
    u64 r; asm("mov.b64 %0, {%1, %2};" : "=l"(r) : "f"(lo), "f"(hi)); return r;
}
__device__ __forceinline__ float2 unpack2(u64 v) {
    float2 f; asm("mov.b64 {%0, %1}, %2;" : "=f"(f.x), "=f"(f.y) : "l"(v)); return f;
}
// Packed dual-fp32 FMA (Blackwell f32x2 pipe)
__device__ __forceinline__ u64 ffma2(u64 a, u64 b, u64 c) {
    u64 d; asm("fma.rn.f32x2 %0, %1, %2, %3;" : "=l"(d) : "l"(a), "l"(b), "l"(c)); return d;
}
__device__ __forceinline__ u64 addx2(u64 a, u64 b) {
    u64 d; asm("add.rn.f32x2 %0, %1, %2;" : "=l"(d) : "l"(a), "l"(b)); return d;
}
__device__ __forceinline__ float sigf(float z) {
    return __fdividef(1.0f, 1.0f + __expf(-z));
}
__device__ __forceinline__ float tanh_fast(float z) {
    return fmaf(2.0f, sigf(2.0f * z), -1.0f);
}

// Horizontal reduce 8 accumulator chains -> 4 gates, then cell update.
__device__ __forceinline__ float cell_finish(
    u64 ai, u64 bi, u64 af, u64 bf, u64 ag, u64 bg, u64 ao, u64 bo, float& c)
{
    float2 p;
    p = unpack2(addx2(ai, bi)); float gi = p.x + p.y;
    p = unpack2(addx2(af, bf)); float gf = p.x + p.y;
    p = unpack2(addx2(ag, bg)); float gg = p.x + p.y;
    p = unpack2(addx2(ao, bo)); float go = p.x + p.y;
    float iv = sigf(gi);
    float fv = sigf(gf);
    float gv = tanh_fast(gg);
    float ov = sigf(go);
    float cn = fmaf(fv, c, iv * gv);
    c = cn;
    return ov * tanh_fast(cn);
}

__global__ __launch_bounds__(TPB, 2)
void lstm_head_kernel(const float* __restrict__ x,
                      const float* __restrict__ W_ih,
                      const float* __restrict__ W_hh,
                      const float* __restrict__ b_ih,
                      const float* __restrict__ b_hh,
                      const float* __restrict__ W_fc,
                      const float* __restrict__ b_fc,
                      float* __restrict__ out,
                      int write_logits, int write_argmax, long long arg_off)
{
    // Weights split by unit-half: half h owns units [h*20, h*20+20).
    // Row (g, jj) of half h lives at Ws[h*HBASE + (g*20+jj)*40 .. +40).
    // HBASE skew (32B) keeps the two halves' broadcasts on disjoint banks.
    __shared__ __align__(16) float Ws[2 * HBASE];    // 25664 B
    __shared__ float win_s[NG];
    __shared__ float b_s[NG];
    __shared__ float Wfc_s[NC * NH];
    __shared__ float bfc_s[NC];
    __shared__ float xs[NT * TPB];                   // 20480 B  [t][local seq]

    const int tid  = threadIdx.x;
    const int pair = tid >> 1;
    const int half = tid & 1;

    for (int i = tid; i < NG * NH; i += TPB) {
        int r = i / NH, k = i % NH;           // global row r = g*40 + j
        int g = r / NH, j = r % NH;
        int hh = j / 20, jj = j % 20;
        Ws[hh * HBASE + (g * 20 + jj) * NH + k] = W_hh[i];
    }
    for (int i = tid; i < NG; i += TPB) {
        win_s[i] = W_ih[i];
        b_s[i]   = b_ih[i] + b_hh[i];
    }
    for (int i = tid; i < NC * NH; i += TPB) Wfc_s[i] = W_fc[i];
    if (tid < NC) bfc_s[tid] = b_fc[tid];

    const long long base = (long long)blockIdx.x * TPB;   // 128 seqs per block
    for (int i = tid; i < TPB * NT; i += TPB) {
        int s = i / NT;
        int t = i % NT;
        xs[t * TPB + s] = x[(base + s) * NT + t];
    }
    __syncthreads();

    const float* Wh = Ws + half * HBASE;
    const int jg = half * 20;     // global unit offset of my first owned unit

    u64 h0[NH / 2], h1[NH / 2];   // full packed h for seqs (2*pair) and (2*pair+1)
    float c0[20], c1[20];         // cell state, my 20 units only
#pragma unroll
    for (int k = 0; k < NH / 2; k++) { h0[k] = 0ULL; h1[k] = 0ULL; }
#pragma unroll
    for (int k = 0; k < 20; k++) { c0[k] = 0.0f; c1[k] = 0.0f; }

#pragma unroll 1
    for (int t = 0; t < NT; t++) {
        const float xt0 = xs[t * TPB + 2 * pair];
        const float xt1 = xs[t * TPB + 2 * pair + 1];
        float hn0[20], hn1[20];

#pragma unroll
        for (int jj = 0; jj < 20; jj++) {
            const int j = jg + jj;   // global unit index (bias / win indexing)
            const ulonglong2* ri = (const ulonglong2*)(Wh + (jj)        * NH);
            const ulonglong2* rf = (const ulonglong2*)(Wh + (20 + jj)   * NH);
            const ulonglong2* rg = (const ulonglong2*)(Wh + (40 + jj)   * NH);
            const ulonglong2* ro = (const ulonglong2*)(Wh + (60 + jj)   * NH);

            u64 ai0 = pack2(fmaf(xt0, win_s[j],          b_s[j]),          0.f), bi0 = 0ULL;
            u64 af0 = pack2(fmaf(xt0, win_s[NH + j],     b_s[NH + j]),     0.f), bf0 = 0ULL;
            u64 ag0 = pack2(fmaf(xt0, win_s[2*NH + j],   b_s[2*NH + j]),   0.f), bg0 = 0ULL;
            u64 ao0 = pack2(fmaf(xt0, win_s[3*NH + j],   b_s[3*NH + j]),   0.f), bo0 = 0ULL;
            u64 ai1 = pack2(fmaf(xt1, win_s[j],          b_s[j]),          0.f), bi1 = 0ULL;
            u64 af1 = pack2(fmaf(xt1, win_s[NH + j],     b_s[NH + j]),     0.f), bf1 = 0ULL;
            u64 ag1 = pack2(fmaf(xt1, win_s[2*NH + j],   b_s[2*NH + j]),   0.f), bg1 = 0ULL;
            u64 ao1 = pack2(fmaf(xt1, win_s[3*NH + j],   b_s[3*NH + j]),   0.f), bo1 = 0ULL;

#pragma unroll
            for (int q = 0; q < NH / 4; q++) {
                ulonglong2 wi = ri[q];
                ulonglong2 wf = rf[q];
                ulonglong2 wg = rg[q];
                ulonglong2 wo = ro[q];
                u64 ha0 = h0[2*q], hb0 = h0[2*q+1];
                u64 ha1 = h1[2*q], hb1 = h1[2*q+1];
                // every weight load feeds BOTH sequences (2x reuse vs v1)
                ai0 = ffma2(ha0, wi.x, ai0); bi0 = ffma2(hb0, wi.y, bi0);
                af0 = ffma2(ha0, wf.x, af0); bf0 = ffma2(hb0, wf.y, bf0);
                ag0 = ffma2(ha0, wg.x, ag0); bg0 = ffma2(hb0, wg.y, bg0);
                ao0 = ffma2(ha0, wo.x, ao0); bo0 = ffma2(hb0, wo.y, bo0);
                ai1 = ffma2(ha1, wi.x, ai1); bi1 = ffma2(hb1, wi.y, bi1);
                af1 = ffma2(ha1, wf.x, af1); bf1 = ffma2(hb1, wf.y, bf1);
                ag1 = ffma2(ha1, wg.x, ag1); bg1 = ffma2(hb1, wg.y, bg1);
                ao1 = ffma2(ha1, wo.x, ao1); bo1 = ffma2(hb1, wo.y, bo1);
            }
            hn0[jj] = cell_finish(ai0, bi0, af0, bf0, ag0, bg0, ao0, bo0, c0[jj]);
            hn1[jj] = cell_finish(ai1, bi1, af1, bf1, ag1, bg1, ao1, bo1, c1[jj]);
        }

        // Exchange the partner thread's 20 units and rebuild packed full h.
#pragma unroll
        for (int k = 0; k < 10; k++) {
            float m0a = hn0[2*k], m0b = hn0[2*k+1];
            float m1a = hn1[2*k], m1b = hn1[2*k+1];
            float o0a = __shfl_xor_sync(0xffffffffu, m0a, 1);
            float o0b = __shfl_xor_sync(0xffffffffu, m0b, 1);
            float o1a = __shfl_xor_sync(0xffffffffu, m1a, 1);
            float o1b = __shfl_xor_sync(0xffffffffu, m1b, 1);
            u64 mine0 = pack2(m0a, m0b), oth0 = pack2(o0a, o0b);
            u64 mine1 = pack2(m1a, m1b), oth1 = pack2(o1a, o1b);
            // units [0,20) belong to half 0, [20,40) to half 1
            h0[k]      = half ? oth0 : mine0;
            h0[10 + k] = half ? mine0 : oth0;
            h1[k]      = half ? oth1 : mine1;
            h1[10 + k] = half ? mine1 : oth1;
        }
    }

    // Final head: thread (pair, half) outputs seq = base + 2*pair + half = base + tid
    float hT[NH];
#pragma unroll
    for (int k = 0; k < NH / 2; k++) {
        float2 a = unpack2(h0[k]);
        float2 b = unpack2(h1[k]);
        hT[2*k]     = half ? b.x : a.x;
        hT[2*k + 1] = half ? b.y : a.y;
    }
    const long long seq = base + tid;
    float best = -3.402823466e38f;
    int bidx = 0;
#pragma unroll
    for (int cls = 0; cls < NC; cls++) {
        float acc = bfc_s[cls];
#pragma unroll
        for (int k = 0; k < NH; k++) acc = fmaf(hT[k], Wfc_s[cls * NH + k], acc);
        if (write_logits) out[seq * NC + cls] = acc;
        if (acc > best) { best = acc; bidx = cls; }
    }
    if (write_argmax) out[arg_off + seq] = (float)bidx;
}

extern "C" void kernel_launch(void* const* d_in, const int* in_sizes, int n_in,
                              void* d_out, int out_size)
{
    const float* x    = (const float*)d_in[0];
    const float* W_ih = (const float*)d_in[1];
    const float* W_hh = (const float*)d_in[2];
    const float* b_ih = (const float*)d_in[3];
    const float* b_hh = (const float*)d_in[4];
    const float* W_fc = (const float*)d_in[5];
    const float* b_fc = (const float*)d_in[6];
    float* out = (float*)d_out;

    const long long B = (long long)in_sizes[0] / NT;

    int write_logits = 1, write_argmax = 0;
    long long arg_off = 0;
    if ((long long)out_size >= B * (NC + 1)) {
        write_logits = 1; write_argmax = 1; arg_off = B * NC;
    } else if ((long long)out_size >= B * NC) {
        write_logits = 1; write_argmax = 0;
    } else {
        write_logits = 0; write_argmax = 1; arg_off = 0;
    }

    const int grid = (int)((B + TPB - 1) / TPB);   // 128 seqs per block
    lstm_head_kernel<<<grid, TPB>>>(x, W_ih, W_hh, b_ih, b_hh, W_fc, b_fc,
                                    out, write_logits, write_argmax, arg_off);
}

// round 5
// speedup vs baseline: 6.6109x; 6.6109x over previous
#include <cuda_runtime.h>

#define TPB 128
#define NH  40
#define NT  40
#define NG  160
#define NC  4
#define HBASE 3208   // floats per half-section: 80 rows * 40 + 8-float bank skew

typedef unsigned long long u64;

__device__ __forceinline__ u64 pack2(float lo, float hi) {
    u64 r; asm("mov.b64 %0, {%1, %2};" : "=l"(r) : "f"(lo), "f"(hi)); return r;
}
__device__ __forceinline__ float2 unpack2(u64 v) {
    float2 f; asm("mov.b64 {%0, %1}, %2;" : "=f"(f.x), "=f"(f.y) : "l"(v)); return f;
}
// Packed dual-fp32 FMA (Blackwell f32x2 pipe)
__device__ __forceinline__ u64 ffma2(u64 a, u64 b, u64 c) {
    u64 d; asm("fma.rn.f32x2 %0, %1, %2, %3;" : "=l"(d) : "l"(a), "l"(b), "l"(c)); return d;
}
__device__ __forceinline__ float sigf(float z) {
    return __fdividef(1.0f, 1.0f + __expf(-z));
}
__device__ __forceinline__ float tanh_fast(float z) {
    return fmaf(2.0f, sigf(2.0f * z), -1.0f);
}

__global__ __launch_bounds__(TPB, 2)
void lstm_head_kernel(const float* __restrict__ x,
                      const float* __restrict__ W_ih,
                      const float* __restrict__ W_hh,
                      const float* __restrict__ b_ih,
                      const float* __restrict__ b_hh,
                      const float* __restrict__ W_fc,
                      const float* __restrict__ b_fc,
                      float* __restrict__ out,
                      int write_logits, int write_argmax, long long arg_off)
{
    // W_hh split by unit-half: half h owns units [h*20, h*20+20).
    // Row (g, jj) of half h lives at Ws[h*HBASE + (g*20+jj)*40 .. +40).
    // HBASE skew (32B) keeps the two halves' 2-address broadcasts on disjoint banks.
    __shared__ __align__(16) float Ws[2 * HBASE];    // 25664 B
    __shared__ float2 winb_s[NG];                    // (W_ih[r], b_ih[r]+b_hh[r])
    __shared__ float  Wfc_s[NC * NH];
    __shared__ float  bfc_s[NC];
    __shared__ float2 hs[NH / 2][130];               // h staging [unit-pair][seq], padded

    const int tid  = threadIdx.x;
    const int pair = tid >> 1;
    const int half = tid & 1;

    for (int i = tid; i < NG * NH; i += TPB) {
        int r = i / NH, k = i % NH;           // global row r = g*40 + j
        int g = r / NH, j = r % NH;
        int hh = j / 20, jj = j % 20;
        Ws[hh * HBASE + (g * 20 + jj) * NH + k] = W_hh[i];
    }
    for (int i = tid; i < NG; i += TPB)
        winb_s[i] = make_float2(W_ih[i], b_ih[i] + b_hh[i]);
    for (int i = tid; i < NC * NH; i += TPB) Wfc_s[i] = W_fc[i];
    if (tid < NC) bfc_s[tid] = b_fc[tid];
    __syncthreads();

    const long long base = (long long)blockIdx.x * TPB;  // 128 seqs per block
    const float* __restrict__ x0 = x + (base + 2 * pair) * NT;      // seq 2p
    const float* __restrict__ x1 = x0 + NT;                          // seq 2p+1

    const float* Wh = Ws + half * HBASE;
    const int jg = half * 20;     // first owned global unit

    u64 h0[NH / 2], h1[NH / 2];   // full packed h for seqs 2p, 2p+1
    float c0[20], c1[20];         // cell state, my 20 units only
#pragma unroll
    for (int k = 0; k < NH / 2; k++) { h0[k] = 0ULL; h1[k] = 0ULL; }
#pragma unroll
    for (int k = 0; k < 20; k++) { c0[k] = 0.0f; c1[k] = 0.0f; }

    float xa = x0[0];
    float xb = x1[0];

#pragma unroll 1
    for (int t = 0; t < NT; t++) {
        const float xt0 = xa, xt1 = xb;
        const int tn = (t < NT - 1) ? (t + 1) : (NT - 1);
        xa = x0[tn];                 // prefetch next step's x
        xb = x1[tn];

        float hp0, hp1;              // staged even-unit h values
#pragma unroll 2
        for (int jj = 0; jj < 20; jj++) {
            const int j = jg + jj;
            const ulonglong2* ri = (const ulonglong2*)(Wh + (jj)      * NH);
            const ulonglong2* rf = (const ulonglong2*)(Wh + (20 + jj) * NH);
            const ulonglong2* rg = (const ulonglong2*)(Wh + (40 + jj) * NH);
            const ulonglong2* ro = (const ulonglong2*)(Wh + (60 + jj) * NH);

            u64 ai0 = 0ULL, af0 = 0ULL, ag0 = 0ULL, ao0 = 0ULL;
            u64 ai1 = 0ULL, af1 = 0ULL, ag1 = 0ULL, ao1 = 0ULL;
#pragma unroll
            for (int q = 0; q < NH / 4; q++) {
                ulonglong2 wi = ri[q];
                ulonglong2 wf = rf[q];
                ulonglong2 wg = rg[q];
                ulonglong2 wo = ro[q];
                u64 ha0 = h0[2*q], hb0 = h0[2*q+1];
                u64 ha1 = h1[2*q], hb1 = h1[2*q+1];
                ai0 = ffma2(ha0, wi.x, ai0); ai1 = ffma2(ha1, wi.x, ai1);
                af0 = ffma2(ha0, wf.x, af0); af1 = ffma2(ha1, wf.x, af1);
                ag0 = ffma2(ha0, wg.x, ag0); ag1 = ffma2(ha1, wg.x, ag1);
                ao0 = ffma2(ha0, wo.x, ao0); ao1 = ffma2(ha1, wo.x, ao1);
                ai0 = ffma2(hb0, wi.y, ai0); ai1 = ffma2(hb1, wi.y, ai1);
                af0 = ffma2(hb0, wf.y, af0); af1 = ffma2(hb1, wf.y, af1);
                ag0 = ffma2(hb0, wg.y, ag0); ag1 = ffma2(hb1, wg.y, ag1);
                ao0 = ffma2(hb0, wo.y, ao0); ao1 = ffma2(hb1, wo.y, ao1);
            }
            const float2 wbi = winb_s[j];
            const float2 wbf = winb_s[NH + j];
            const float2 wbg = winb_s[2 * NH + j];
            const float2 wbo = winb_s[3 * NH + j];
            float2 p;
            // seq 0
            p = unpack2(ai0); float gi0 = (p.x + p.y) + fmaf(xt0, wbi.x, wbi.y);
            p = unpack2(af0); float gf0 = (p.x + p.y) + fmaf(xt0, wbf.x, wbf.y);
            p = unpack2(ag0); float gg0 = (p.x + p.y) + fmaf(xt0, wbg.x, wbg.y);
            p = unpack2(ao0); float go0 = (p.x + p.y) + fmaf(xt0, wbo.x, wbo.y);
            float cn0 = fmaf(sigf(gf0), c0[jj], sigf(gi0) * tanh_fast(gg0));
            c0[jj] = cn0;
            float hv0 = sigf(go0) * tanh_fast(cn0);
            // seq 1
            p = unpack2(ai1); float gi1 = (p.x + p.y) + fmaf(xt1, wbi.x, wbi.y);
            p = unpack2(af1); float gf1 = (p.x + p.y) + fmaf(xt1, wbf.x, wbf.y);
            p = unpack2(ag1); float gg1 = (p.x + p.y) + fmaf(xt1, wbg.x, wbg.y);
            p = unpack2(ao1); float go1 = (p.x + p.y) + fmaf(xt1, wbo.x, wbo.y);
            float cn1 = fmaf(sigf(gf1), c1[jj], sigf(gi1) * tanh_fast(gg1));
            c1[jj] = cn1;
            float hv1 = sigf(go1) * tanh_fast(cn1);

            if ((jj & 1) == 0) {
                hp0 = hv0; hp1 = hv1;
            } else {
                const int kp = 10 * half + (jj >> 1);
                hs[kp][2 * pair]     = make_float2(hp0, hv0);
                hs[kp][2 * pair + 1] = make_float2(hp1, hv1);
            }
        }

        __syncwarp();
#pragma unroll
        for (int k = 0; k < NH / 2; k++) {
            float2 v0 = hs[k][2 * pair];
            float2 v1 = hs[k][2 * pair + 1];
            h0[k] = pack2(v0.x, v0.y);
            h1[k] = pack2(v1.x, v1.y);
        }
        __syncwarp();
    }

    // Final head: thread tid = 2p+half outputs seq base+tid using h(half)
    float hT[NH];
#pragma unroll
    for (int k = 0; k < NH / 2; k++) {
        float2 a = unpack2(half ? h1[k] : h0[k]);
        hT[2 * k]     = a.x;
        hT[2 * k + 1] = a.y;
    }
    const long long seq = base + tid;
    float best = -3.402823466e38f;
    int bidx = 0;
#pragma unroll
    for (int cls = 0; cls < NC; cls++) {
        float acc = bfc_s[cls];
#pragma unroll
        for (int k = 0; k < NH; k++) acc = fmaf(hT[k], Wfc_s[cls * NH + k], acc);
        if (write_logits) out[seq * NC + cls] = acc;
        if (acc > best) { best = acc; bidx = cls; }
    }
    if (write_argmax) out[arg_off + seq] = (float)bidx;
}

extern "C" void kernel_launch(void* const* d_in, const int* in_sizes, int n_in,
                              void* d_out, int out_size)
{
    const float* x    = (const float*)d_in[0];
    const float* W_ih = (const float*)d_in[1];
    const float* W_hh = (const float*)d_in[2];
    const float* b_ih = (const float*)d_in[3];
    const float* b_hh = (const float*)d_in[4];
    const float* W_fc = (const float*)d_in[5];
    const float* b_fc = (const float*)d_in[6];
    float* out = (float*)d_out;

    const long long B = (long long)in_sizes[0] / NT;

    int write_logits = 1, write_argmax = 0;
    long long arg_off = 0;
    if ((long long)out_size >= B * (NC + 1)) {
        write_logits = 1; write_argmax = 1; arg_off = B * NC;
    } else if ((long long)out_size >= B * NC) {
        write_logits = 1; write_argmax = 0;
    } else {
        write_logits = 0; write_argmax = 1; arg_off = 0;
    }

    const int grid = (int)((B + TPB - 1) / TPB);   // 128 seqs per block
    lstm_head_kernel<<<grid, TPB>>>(x, W_ih, W_hh, b_ih, b_hh, W_fc, b_fc,
                                    out, write_logits, write_argmax, arg_off);
}

// round 6
// speedup vs baseline: 6.6946x; 1.0127x over previous
#include <cuda_runtime.h>

#define TPB 128
#define NH  40
#define NT  40
#define NG  160
#define NC  4
#define HBASE 3208   // floats per half-section: 80 rows * 40 + 8-float bank skew

typedef unsigned long long u64;

__device__ __forceinline__ u64 pack2(float lo, float hi) {
    u64 r; asm("mov.b64 %0, {%1, %2};" : "=l"(r) : "f"(lo), "f"(hi)); return r;
}
__device__ __forceinline__ float2 unpack2(u64 v) {
    float2 f; asm("mov.b64 {%0, %1}, %2;" : "=f"(f.x), "=f"(f.y) : "l"(v)); return f;
}
// Packed dual-fp32 FMA (Blackwell f32x2 pipe)
__device__ __forceinline__ u64 ffma2(u64 a, u64 b, u64 c) {
    u64 d; asm("fma.rn.f32x2 %0, %1, %2, %3;" : "=l"(d) : "l"(a), "l"(b), "l"(c)); return d;
}
__device__ __forceinline__ float sigf(float z) {
    return __fdividef(1.0f, 1.0f + __expf(-z));
}
__device__ __forceinline__ float tanh_fast(float z) {
    return fmaf(2.0f, sigf(2.0f * z), -1.0f);
}

__global__ __launch_bounds__(TPB, 3)
void lstm_head_kernel(const float* __restrict__ x,
                      const float* __restrict__ W_ih,
                      const float* __restrict__ W_hh,
                      const float* __restrict__ b_ih,
                      const float* __restrict__ b_hh,
                      const float* __restrict__ W_fc,
                      const float* __restrict__ b_fc,
                      float* __restrict__ out,
                      int write_logits, int write_argmax, long long arg_off)
{
    // W_hh split by unit-half: half h owns units [h*20, h*20+20).
    // Row (g, jj) of half h lives at Ws[h*HBASE + (g*20+jj)*40 .. +40).
    // HBASE skew (32B) keeps the two halves' 2-address broadcasts on disjoint banks.
    __shared__ __align__(16) float Ws[2 * HBASE];    // 25664 B
    __shared__ float2 winb_s[NG];                    // (W_ih[r], b_ih[r]+b_hh[r])
    __shared__ float  Wfc_s[NC * NH];
    __shared__ float  bfc_s[NC];
    __shared__ float2 hs[NH / 2][130];               // h staging [unit-pair][seq], padded

    const int tid  = threadIdx.x;
    const int pair = tid >> 1;
    const int half = tid & 1;

    for (int i = tid; i < NG * NH; i += TPB) {
        int r = i / NH, k = i % NH;           // global row r = g*40 + j
        int g = r / NH, j = r % NH;
        int hh = j / 20, jj = j % 20;
        Ws[hh * HBASE + (g * 20 + jj) * NH + k] = W_hh[i];
    }
    for (int i = tid; i < NG; i += TPB)
        winb_s[i] = make_float2(W_ih[i], b_ih[i] + b_hh[i]);
    for (int i = tid; i < NC * NH; i += TPB) Wfc_s[i] = W_fc[i];
    if (tid < NC) bfc_s[tid] = b_fc[tid];
    __syncthreads();

    const long long base = (long long)blockIdx.x * TPB;  // 128 seqs per block
    const float* __restrict__ x0 = x + (base + 2 * pair) * NT;      // seq 2p
    const float* __restrict__ x1 = x0 + NT;                          // seq 2p+1

    const float* Wh = Ws + half * HBASE;
    const int jg = half * 20;     // first owned global unit

    u64 h0[NH / 2], h1[NH / 2];   // full packed h for seqs 2p, 2p+1
    float c0[20], c1[20];         // cell state, my 20 units only
#pragma unroll
    for (int k = 0; k < NH / 2; k++) { h0[k] = 0ULL; h1[k] = 0ULL; }
#pragma unroll
    for (int k = 0; k < 20; k++) { c0[k] = 0.0f; c1[k] = 0.0f; }

    float xa = x0[0];
    float xb = x1[0];

#pragma unroll 1
    for (int t = 0; t < NT; t++) {
        const float xt0 = xa, xt1 = xb;
        const int tn = (t < NT - 1) ? (t + 1) : (NT - 1);
        xa = x0[tn];                 // prefetch next step's x
        xb = x1[tn];

        float hp0, hp1;              // staged even-unit h values
#pragma unroll 2
        for (int jj = 0; jj < 20; jj++) {
            const int j = jg + jj;
            const ulonglong2* ri = (const ulonglong2*)(Wh + (jj)      * NH);
            const ulonglong2* rf = (const ulonglong2*)(Wh + (20 + jj) * NH);
            const ulonglong2* rg = (const ulonglong2*)(Wh + (40 + jj) * NH);
            const ulonglong2* ro = (const ulonglong2*)(Wh + (60 + jj) * NH);

            // Hoisted: bias/input weights load early so LDS latency hides
            // under the FFMA2 block instead of stalling the gate finish.
            const float2 wbi = winb_s[j];
            const float2 wbf = winb_s[NH + j];
            const float2 wbg = winb_s[2 * NH + j];
            const float2 wbo = winb_s[3 * NH + j];

            u64 ai0 = 0ULL, af0 = 0ULL, ag0 = 0ULL, ao0 = 0ULL;
            u64 ai1 = 0ULL, af1 = 0ULL, ag1 = 0ULL, ao1 = 0ULL;
#pragma unroll
            for (int q = 0; q < NH / 4; q++) {
                ulonglong2 wi = ri[q];
                ulonglong2 wf = rf[q];
                ulonglong2 wg = rg[q];
                ulonglong2 wo = ro[q];
                u64 ha0 = h0[2*q], hb0 = h0[2*q+1];
                u64 ha1 = h1[2*q], hb1 = h1[2*q+1];
                ai0 = ffma2(ha0, wi.x, ai0); ai1 = ffma2(ha1, wi.x, ai1);
                af0 = ffma2(ha0, wf.x, af0); af1 = ffma2(ha1, wf.x, af1);
                ag0 = ffma2(ha0, wg.x, ag0); ag1 = ffma2(ha1, wg.x, ag1);
                ao0 = ffma2(ha0, wo.x, ao0); ao1 = ffma2(ha1, wo.x, ao1);
                ai0 = ffma2(hb0, wi.y, ai0); ai1 = ffma2(hb1, wi.y, ai1);
                af0 = ffma2(hb0, wf.y, af0); af1 = ffma2(hb1, wf.y, af1);
                ag0 = ffma2(hb0, wg.y, ag0); ag1 = ffma2(hb1, wg.y, ag1);
                ao0 = ffma2(hb0, wo.y, ao0); ao1 = ffma2(hb1, wo.y, ao1);
            }
            float2 p;
            // seq 0
            p = unpack2(ai0); float gi0 = (p.x + p.y) + fmaf(xt0, wbi.x, wbi.y);
            p = unpack2(af0); float gf0 = (p.x + p.y) + fmaf(xt0, wbf.x, wbf.y);
            p = unpack2(ag0); float gg0 = (p.x + p.y) + fmaf(xt0, wbg.x, wbg.y);
            p = unpack2(ao0); float go0 = (p.x + p.y) + fmaf(xt0, wbo.x, wbo.y);
            float cn0 = fmaf(sigf(gf0), c0[jj], sigf(gi0) * tanh_fast(gg0));
            c0[jj] = cn0;
            float hv0 = sigf(go0) * tanh_fast(cn0);
            // seq 1
            p = unpack2(ai1); float gi1 = (p.x + p.y) + fmaf(xt1, wbi.x, wbi.y);
            p = unpack2(af1); float gf1 = (p.x + p.y) + fmaf(xt1, wbf.x, wbf.y);
            p = unpack2(ag1); float gg1 = (p.x + p.y) + fmaf(xt1, wbg.x, wbg.y);
            p = unpack2(ao1); float go1 = (p.x + p.y) + fmaf(xt1, wbo.x, wbo.y);
            float cn1 = fmaf(sigf(gf1), c1[jj], sigf(gi1) * tanh_fast(gg1));
            c1[jj] = cn1;
            float hv1 = sigf(go1) * tanh_fast(cn1);

            if ((jj & 1) == 0) {
                hp0 = hv0; hp1 = hv1;
            } else {
                const int kp = 10 * half + (jj >> 1);
                hs[kp][2 * pair]     = make_float2(hp0, hv0);
                hs[kp][2 * pair + 1] = make_float2(hp1, hv1);
            }
        }

        __syncwarp();
#pragma unroll
        for (int k = 0; k < NH / 2; k++) {
            float2 v0 = hs[k][2 * pair];
            float2 v1 = hs[k][2 * pair + 1];
            h0[k] = pack2(v0.x, v0.y);
            h1[k] = pack2(v1.x, v1.y);
        }
        __syncwarp();
    }

    // Final head: thread tid = 2p+half outputs seq base+tid using h(half)
    float hT[NH];
#pragma unroll
    for (int k = 0; k < NH / 2; k++) {
        float2 a = unpack2(half ? h1[k] : h0[k]);
        hT[2 * k]     = a.x;
        hT[2 * k + 1] = a.y;
    }
    const long long seq = base + tid;
    float best = -3.402823466e38f;
    int bidx = 0;
#pragma unroll
    for (int cls = 0; cls < NC; cls++) {
        float acc = bfc_s[cls];
#pragma unroll
        for (int k = 0; k < NH; k++) acc = fmaf(hT[k], Wfc_s[cls * NH + k], acc);
        if (write_logits) out[seq * NC + cls] = acc;
        if (acc > best) { best = acc; bidx = cls; }
    }
    if (write_argmax) out[arg_off + seq] = (float)bidx;
}

extern "C" void kernel_launch(void* const* d_in, const int* in_sizes, int n_in,
                              void* d_out, int out_size)
{
    const float* x    = (const float*)d_in[0];
    const float* W_ih = (const float*)d_in[1];
    const float* W_hh = (const float*)d_in[2];
    const float* b_ih = (const float*)d_in[3];
    const float* b_hh = (const float*)d_in[4];
    const float* W_fc = (const float*)d_in[5];
    const float* b_fc = (const float*)d_in[6];
    float* out = (float*)d_out;

    const long long B = (long long)in_sizes[0] / NT;

    int write_logits = 1, write_argmax = 0;
    long long arg_off = 0;
    if ((long long)out_size >= B * (NC + 1)) {
        write_logits = 1; write_argmax = 1; arg_off = B * NC;
    } else if ((long long)out_size >= B * NC) {
        write_logits = 1; write_argmax = 0;
    } else {
        write_logits = 0; write_argmax = 1; arg_off = 0;
    }

    const int grid = (int)((B + TPB - 1) / TPB);   // 128 seqs per block
    lstm_head_kernel<<<grid, TPB>>>(x, W_ih, W_hh, b_ih, b_hh, W_fc, b_fc,
                                    out, write_logits, write_argmax, arg_off);
}